// round 15
// baseline (speedup 1.0000x reference)
#include <cuda_runtime.h>
#include <cuda_bf16.h>
#include <stdint.h>

// ---------------------------------------------------------------------------
// Problem constants
// ---------------------------------------------------------------------------
#define N_ROWS   16384
#define DDIM     17          // DATA_DIM+1
#define DH       64
#define LEN_M    1088
#define M_PRI    65
#define M0       100
#define M1       100
#define PRED_ELEMS (16384UL * 100UL * 100UL)   // 163,840,000

#define ZS_STRIDE  72
#define NBLKS      256            // 16384/64 n-blocks
#define NTILES     (M0 * NBLKS)   // 25600
#define GRID_MAIN  592            // 148 SMs x 4 resident CTAs

#define NTC        13             // 13 n8 col-tiles covering 104 padded cols
#define W1F_FLOATS (8 * NTC * 4 * 8 * 2)   // 6656
#define W1B_FLOATS 104

// Scratch (allocation-free: __device__ globals)
__device__ float g_W0T[M0 * LEN_M];      // [m][d*64+h] contiguous per m
__device__ float g_W1F[W1F_FLOATS];      // fragment-packed W1 (rows 1..64), tf32
__device__ float g_W1B[W1B_FLOATS];      // bias row 0, exact fp32 (pad 0)
__device__ float g_XT [DDIM * N_ROWS];   // [d][n] transposed x

// ---------------------------------------------------------------------------
// Threefry-2x32 (JAX convention, 20 rounds)
// ---------------------------------------------------------------------------
__host__ __device__ inline uint32_t rotl32(uint32_t x, int r) {
    return (x << r) | (x >> (32 - r));
}

__host__ __device__ inline void threefry2x32(uint32_t k0, uint32_t k1,
                                             uint32_t x0, uint32_t x1,
                                             uint32_t* o0, uint32_t* o1) {
    uint32_t ks0 = k0, ks1 = k1, ks2 = 0x1BD11BDAu ^ k0 ^ k1;
    x0 += ks0; x1 += ks1;
#define TF_ROUND(r) { x0 += x1; x1 = rotl32(x1, r); x1 ^= x0; }
    TF_ROUND(13) TF_ROUND(15) TF_ROUND(26) TF_ROUND(6)
    x0 += ks1; x1 += ks2 + 1u;
    TF_ROUND(17) TF_ROUND(29) TF_ROUND(16) TF_ROUND(24)
    x0 += ks2; x1 += ks0 + 2u;
    TF_ROUND(13) TF_ROUND(15) TF_ROUND(26) TF_ROUND(6)
    x0 += ks0; x1 += ks1 + 3u;
    TF_ROUND(17) TF_ROUND(29) TF_ROUND(16) TF_ROUND(24)
    x0 += ks1; x1 += ks2 + 4u;
    TF_ROUND(13) TF_ROUND(15) TF_ROUND(26) TF_ROUND(6)
    x0 += ks2; x1 += ks0 + 5u;
#undef TF_ROUND
    *o0 = x0; *o1 = x1;
}

__device__ inline uint32_t random_bits_partitionable(uint32_t k0, uint32_t k1,
                                                     uint32_t i) {
    uint32_t o0, o1;
    threefry2x32(k0, k1, 0u, i, &o0, &o1);
    return o0 ^ o1;
}

// JAX normal: bits -> uniform in [-0.99999994, 1) -> sqrt(2)*erfinv(u)
__device__ inline float bits_to_normal(uint32_t bits) {
    float f = __uint_as_float((bits >> 9) | 0x3f800000u) - 1.0f;  // [0,1)
    const float lo = -0.99999994f;
    float u = fmaxf(lo, __fadd_rn(__fmul_rn(f, 2.0f), lo));
    return 1.41421356f * erfinvf(u);
}

// round-to-nearest tf32
__device__ inline float tf32_rna(float x) {
    uint32_t o;
    asm("cvt.rna.tf32.f32 %0, %1;" : "=r"(o) : "f"(x));
    return __uint_as_float(o);
}

// 16-byte async copy global -> shared (no destination registers)
__device__ __forceinline__ void cp_async16(uint32_t smem_addr, const void* gptr) {
    asm volatile("cp.async.ca.shared.global [%0], [%1], 16;"
                 :: "r"(smem_addr), "l"(gptr));
}

// W1 sample value (rows 0..64 of samps_w1), c < 100
__device__ inline float sample_w1(const float* __restrict__ ms_vs,
                                  uint32_t k0, uint32_t k1, int r, int c) {
    uint32_t bits = random_bits_partitionable(k0, k1, (uint32_t)(r * M1 + c));
    float mean = ms_vs[LEN_M + r];
    float var  = fabsf(ms_vs[2 * LEN_M + M_PRI + r]) + 1e-6f;
    return mean + bits_to_normal(bits) * sqrtf(var);
}

// ---------------------------------------------------------------------------
// Prep kernels
// ---------------------------------------------------------------------------
__global__ void gen_w0_kernel(const float* __restrict__ ms_vs,
                              uint32_t k0, uint32_t k1) {
    int i = blockIdx.x * blockDim.x + threadIdx.x;   // flat idx in (1088,100)
    if (i >= LEN_M * M0) return;
    uint32_t bits = random_bits_partitionable(k0, k1, (uint32_t)i);
    int r = i / M0;            // d*64 + h
    int c = i % M0;            // m
    float mean = ms_vs[r];
    float var  = fabsf(ms_vs[LEN_M + M_PRI + r]) + 1e-6f;
    float val  = mean + bits_to_normal(bits) * sqrtf(var);
    g_W0T[c * LEN_M + r] = val;
}

// Fragment-packed W1: pair index p over [kt][gtc][tig][grp] (3328 pairs).
// Pair = (W1[1+8kt+tig][c], W1[1+8kt+tig+4][c]), c = 8*gtc+grp, tf32-rounded.
// Also fills bias row g_W1B (exact fp32).
__global__ void gen_w1_kernel(const float* __restrict__ ms_vs,
                              uint32_t k0, uint32_t k1) {
    int p = blockIdx.x * blockDim.x + threadIdx.x;
    if (p < 8 * NTC * 4 * 8) {
        int grp = p & 7;
        int tig = (p >> 3) & 3;
        int gtc = (p >> 5) % NTC;
        int kt  = p / (NTC * 32);
        int c   = 8 * gtc + grp;
        int r1  = 1 + 8 * kt + tig;
        int r2  = r1 + 4;
        float v0 = 0.0f, v1 = 0.0f;
        if (c < M1) {
            v0 = tf32_rna(sample_w1(ms_vs, k0, k1, r1, c));
            v1 = tf32_rna(sample_w1(ms_vs, k0, k1, r2, c));
        }
        g_W1F[p * 2]     = v0;
        g_W1F[p * 2 + 1] = v1;
    }
    if (p < W1B_FLOATS) {
        g_W1B[p] = (p < M1) ? sample_w1(ms_vs, k0, k1, 0, p) : 0.0f;
    }
}

// transpose x -> g_XT[d][n] (writes coalesced)
__global__ void transpose_x_kernel(const float* __restrict__ x) {
    int i = blockIdx.x * blockDim.x + threadIdx.x;   // over 17*16384, d-major
    if (i >= DDIM * N_ROWS) return;
    int d = i / N_ROWS;
    int n = i - d * N_ROWS;
    g_XT[i] = x[n * DDIM + d];
}

__global__ void tail_kernel(const float* __restrict__ ms_vs, float* __restrict__ out) {
    int i = blockIdx.x * blockDim.x + threadIdx.x;
    size_t P = PRED_ELEMS;
    if (i < LEN_M) {
        out[P + i]         = ms_vs[i];
        out[P + LEN_M + i] = fabsf(ms_vs[LEN_M + M_PRI + i]) + 1e-6f;
    }
    if (i < M_PRI) {
        out[P + 2 * LEN_M + i]         = ms_vs[LEN_M + i];
        out[P + 2 * LEN_M + M_PRI + i] = fabsf(ms_vs[2 * LEN_M + M_PRI + i]) + 1e-6f;
    }
}

// ---------------------------------------------------------------------------
// Phase-2 MMA helper: B operands from fragment-packed smem (1 LDS.64 each)
// gtc0 = first global col-tile for this warp group; cb0 = 8*gtc0
// ---------------------------------------------------------------------------
template<int NT>
__device__ __forceinline__ void phase2_mma(const float* __restrict__ zs,
                                           const float2* __restrict__ w1f,
                                           const float* __restrict__ w1b,
                                           float* __restrict__ out,
                                           int n0, int m, int lane, int rg, int gtc0) {
    const int tig = lane & 3;    // thread-in-group
    const int grp = lane >> 2;   // group id (0..7)
    const int cb0 = 8 * gtc0;

    float acc[NT][4];
    // accumulator init = bias row (exact fp32), float2 loads
#pragma unroll
    for (int tc = 0; tc < NT; tc++) {
        int cc = cb0 + 8 * tc + 2 * tig;
        float2 b = *(const float2*)&w1b[cc];
        acc[tc][0] = b.x; acc[tc][1] = b.y;
        acc[tc][2] = b.x; acc[tc][3] = b.y;
    }

    const int arow = rg * 16 + grp;
    const float*  za  = zs + tig * ZS_STRIDE + arow;
    const float2* wbf = w1f + gtc0 * 32 + tig * 8 + grp;

#pragma unroll
    for (int kt = 0; kt < 8; kt++) {
        const int zk = kt * 8 * ZS_STRIDE;
        uint32_t a0 = __float_as_uint(za[zk]);
        uint32_t a1 = __float_as_uint(za[zk + 8]);
        uint32_t a2 = __float_as_uint(za[zk + 4 * ZS_STRIDE]);
        uint32_t a3 = __float_as_uint(za[zk + 4 * ZS_STRIDE + 8]);
#pragma unroll
        for (int tc = 0; tc < NT; tc++) {
            float2 bf = wbf[(kt * NTC + tc) * 32];
            uint32_t b0 = __float_as_uint(bf.x);
            uint32_t b1 = __float_as_uint(bf.y);
            asm volatile(
                "mma.sync.aligned.m16n8k8.row.col.f32.tf32.tf32.f32 "
                "{%0,%1,%2,%3}, {%4,%5,%6,%7}, {%8,%9}, {%0,%1,%2,%3};"
                : "+f"(acc[tc][0]), "+f"(acc[tc][1]),
                  "+f"(acc[tc][2]), "+f"(acc[tc][3])
                : "r"(a0), "r"(a1), "r"(a2), "r"(a3), "r"(b0), "r"(b1));
        }
    }

    // epilogue: out[n*10000 + m*100 + c], 32-bit indexing
    uint32_t base0 = (uint32_t)(n0 + rg * 16 + grp) * 10000u + (uint32_t)m * 100u;
    uint32_t base1 = base0 + 80000u;   // +8 rows
#pragma unroll
    for (int tc = 0; tc < NT; tc++) {
        int cc = cb0 + 8 * tc + 2 * tig;
        if (cc < M1) {   // cc even; cc<100 implies cc+1<=99
            *(float2*)&out[base0 + cc] = make_float2(acc[tc][0], acc[tc][1]);
            *(float2*)&out[base1 + cc] = make_float2(acc[tc][2], acc[tc][3]);
        }
    }
}

// ---------------------------------------------------------------------------
// Persistent main kernel (stride mapping; cp.async staging in phase-2 slot)
// ---------------------------------------------------------------------------
__global__ __launch_bounds__(256, 4)
void main_kernel(float* __restrict__ out) {
    extern __shared__ float sm[];
    float* xs  = sm;                        // [17][64]    1088  (transposed x tile)
    float* w0s = xs + 1088;                 // [17][64]    1088
    float* zs  = w0s + 1088;                // [64][72]    4608
    float* w1f = zs + 64 * ZS_STRIDE;       // fragments   6656
    float* w1b = w1f + W1F_FLOATS;          // bias        104
    // total 13544 floats = 54176 B -> 4 CTAs/SM

    const int t    = threadIdx.x;
    const int lane = t & 31;
    const int warp = t >> 5;
    const int rg   = warp & 3;
    const int cg   = warp >> 2;
    const int tn   = t & 15, th = t >> 4;
    const int nb   = tn * 4, hb = th * 4;

    const uint32_t xs_s  = (uint32_t)__cvta_generic_to_shared(xs);
    const uint32_t w0s_s = (uint32_t)__cvta_generic_to_shared(w0s);

    // --- stage W1 fragments + bias once per CTA
    {
        const float4* wfg = (const float4*)g_W1F;
        float4* wfd = (float4*)w1f;
#pragma unroll 1
        for (int i = t; i < W1F_FLOATS / 4; i += 256) wfd[i] = wfg[i];   // 1664
        if (t < W1B_FLOATS / 4)
            ((float4*)w1b)[t] = ((const float4*)g_W1B)[t];               // 26
    }

    // --- stage first tile synchronously
    {
        const int w0i = blockIdx.x;
        if (w0i < NTILES) {
            const int m0  = w0i >> 8;
            const int nn0 = (w0i & 255) * 64;
            const float4* w0g = (const float4*)(g_W0T + (size_t)m0 * LEN_M);
            float4* w0d = (float4*)w0s;
            float4* xsd = (float4*)xs;
#pragma unroll 1
            for (int i = t; i < 272; i += 256) {
                int d = i >> 4, q = i & 15;
                xsd[i] = *(const float4*)(g_XT + d * N_ROWS + nn0 + q * 4);
                w0d[i] = w0g[i];
            }
        }
    }
    __syncthreads();

    // --- persistent loop
#pragma unroll 1
    for (int w = blockIdx.x; w < NTILES; w += GRID_MAIN) {
        const int m  = w >> 8;
        const int n0 = (w & 255) * 64;

        // --- phase 1: thread computes 4n x 4h block of Z (fma pipe)
        {
            float acc[4][4];
#pragma unroll
            for (int i = 0; i < 4; i++)
#pragma unroll
                for (int j = 0; j < 4; j++) acc[i][j] = 0.0f;

#pragma unroll
            for (int d = 0; d < DDIM; d++) {
                float4 w4 = *(const float4*)&w0s[d * 64 + hb];
                float4 x4 = *(const float4*)&xs [d * 64 + nb];
                float wv[4] = {w4.x, w4.y, w4.z, w4.w};
                float xv[4] = {x4.x, x4.y, x4.z, x4.w};
#pragma unroll
                for (int i = 0; i < 4; i++)
#pragma unroll
                    for (int j = 0; j < 4; j++) acc[i][j] += xv[i] * wv[j];
            }
#pragma unroll
            for (int j = 0; j < 4; j++) {
                float4 v;
                v.x = tf32_rna(fmaxf(acc[0][j], 0.0f));
                v.y = tf32_rna(fmaxf(acc[1][j], 0.0f));
                v.z = tf32_rna(fmaxf(acc[2][j], 0.0f));
                v.w = tf32_rna(fmaxf(acc[3][j], 0.0f));
                *(float4*)&zs[(hb + j) * ZS_STRIDE + nb] = v;
            }
        }
        __syncthreads();   // zs ready; phase-1 reads of xs/w0s done

        // --- async-stage NEXT tile's xs/w0 into smem (overlaps phase 2)
        const int wn = w + GRID_MAIN;
        if (wn < NTILES) {
            const int nm  = wn >> 8;
            const int nn0 = (wn & 255) * 64;
            const float* w0g = g_W0T + (size_t)nm * LEN_M;
#pragma unroll 1
            for (int i = t; i < 272; i += 256) {
                int d = i >> 4, q = i & 15;
                cp_async16(xs_s  + i * 16, g_XT + d * N_ROWS + nn0 + q * 4);
                cp_async16(w0s_s + i * 16, w0g + i * 4);
            }
        }
        asm volatile("cp.async.commit_group;" ::: "memory");

        // --- phase 2: tensor pipe (reads zs/w1f/w1b only)
        if (cg == 0) phase2_mma<7>(zs, (const float2*)w1f, w1b, out, n0, m, lane, rg, 0);
        else         phase2_mma<6>(zs, (const float2*)w1f, w1b, out, n0, m, lane, rg, 7);

        asm volatile("cp.async.wait_group 0;" ::: "memory");
        __syncthreads();   // staged xs/w0 visible; phase-2 zs reads done
    }
}

// ---------------------------------------------------------------------------
// Launch
// ---------------------------------------------------------------------------
extern "C" void kernel_launch(void* const* d_in, const int* in_sizes, int n_in,
                              void* d_out, int out_size) {
    const float* x     = (const float*)d_in[0];
    const float* ms_vs = (const float*)d_in[1];
    float* out = (float*)d_out;

    // Partitionable threefry split of key(42) = (0, 42)
    uint32_t k0a, k0b, k1a, k1b;
    threefry2x32(0u, 42u, 0u, 0u, &k0a, &k0b);   // child 0 (eps0)
    threefry2x32(0u, 42u, 0u, 1u, &k1a, &k1b);   // child 1 (eps1)

    gen_w0_kernel<<<(LEN_M * M0 + 255) / 256, 256>>>(ms_vs, k0a, k0b);
    gen_w1_kernel<<<(8 * NTC * 4 * 8 + 255) / 256, 256>>>(ms_vs, k1a, k1b);
    transpose_x_kernel<<<(DDIM * N_ROWS + 255) / 256, 256>>>(x);
    tail_kernel<<<(LEN_M + 255) / 256, 256>>>(ms_vs, out);

    const int smem_bytes = (1088 + 1088 + 64 * ZS_STRIDE + W1F_FLOATS + W1B_FLOATS) * 4;
    cudaFuncSetAttribute(main_kernel, cudaFuncAttributeMaxDynamicSharedMemorySize, smem_bytes);
    main_kernel<<<GRID_MAIN, 256, smem_bytes>>>(out);
}